// round 1
// baseline (speedup 1.0000x reference)
#include <cuda_runtime.h>
#include <cuda_bf16.h>
#include <math.h>

// ----------------------------------------------------------------------------
// Problem constants
// ----------------------------------------------------------------------------
#define S_LEN   2048
#define DMODEL  2048
#define HQ      32
#define HKV     8
#define HD      64
#define KV_DIM  (HKV*HD)   // 512

// Scratch (static __device__ arrays: allocation-free)
__device__ float g_h[S_LEN * DMODEL];
__device__ float g_q[S_LEN * DMODEL];
__device__ float g_k[S_LEN * KV_DIM];
__device__ float g_v[S_LEN * KV_DIM];
__device__ float g_o[S_LEN * DMODEL];

// ----------------------------------------------------------------------------
// RMSNorm: one block per row
// ----------------------------------------------------------------------------
__global__ void rmsnorm_kernel(const float* __restrict__ x,
                               const float* __restrict__ g,
                               float* __restrict__ h) {
    const int s = blockIdx.x;
    const float* xr = x + (size_t)s * DMODEL;
    float sum = 0.f;
    for (int d = threadIdx.x; d < DMODEL; d += 256) {
        float v = xr[d];
        sum += v * v;
    }
    __shared__ float red[8];
    #pragma unroll
    for (int o = 16; o > 0; o >>= 1) sum += __shfl_xor_sync(0xffffffffu, sum, o);
    if ((threadIdx.x & 31) == 0) red[threadIdx.x >> 5] = sum;
    __syncthreads();
    if (threadIdx.x < 32) {
        float v = (threadIdx.x < 8) ? red[threadIdx.x] : 0.f;
        #pragma unroll
        for (int o = 4; o > 0; o >>= 1) v += __shfl_xor_sync(0xffffffffu, v, o);
        if (threadIdx.x == 0) red[0] = v;
    }
    __syncthreads();
    const float rinv = rsqrtf(red[0] / (float)DMODEL + 1e-9f);
    for (int d = threadIdx.x; d < DMODEL; d += 256)
        h[(size_t)s * DMODEL + d] = xr[d] * rinv * g[d];
}

// ----------------------------------------------------------------------------
// Generic fp32 GEMM: C[M,N] = A[M,K] @ B[K,N] (+ Res). 64x64 tile, BK=16.
// 256 threads, each computes a 4x4 micro-tile.
// ----------------------------------------------------------------------------
__global__ __launch_bounds__(256) void gemm_kernel(
    const float* __restrict__ A, const float* __restrict__ B,
    const float* __restrict__ Res, float* __restrict__ C,
    int M, int N, int K) {
    __shared__ float As[16][65];
    __shared__ float Bs[16][65];
    const int bm = blockIdx.y * 64, bn = blockIdx.x * 64;
    const int tid = threadIdx.x;
    const int tx = tid & 15, ty = tid >> 4;
    float c[4][4] = {};
    for (int k0 = 0; k0 < K; k0 += 16) {
        #pragma unroll
        for (int i = 0; i < 4; i++) {
            int idx = tid + i * 256;
            int r  = idx >> 4, cc = idx & 15;
            As[cc][r] = A[(size_t)(bm + r) * K + k0 + cc];
            int r2 = idx >> 6, c2 = idx & 63;
            Bs[r2][c2] = B[(size_t)(k0 + r2) * N + bn + c2];
        }
        __syncthreads();
        #pragma unroll
        for (int kk = 0; kk < 16; kk++) {
            float a[4], b[4];
            #pragma unroll
            for (int i = 0; i < 4; i++) a[i] = As[kk][ty * 4 + i];
            #pragma unroll
            for (int j = 0; j < 4; j++) b[j] = Bs[kk][tx * 4 + j];
            #pragma unroll
            for (int i = 0; i < 4; i++)
                #pragma unroll
                for (int j = 0; j < 4; j++)
                    c[i][j] = fmaf(a[i], b[j], c[i][j]);
        }
        __syncthreads();
    }
    #pragma unroll
    for (int i = 0; i < 4; i++) {
        int row = bm + ty * 4 + i;
        #pragma unroll
        for (int j = 0; j < 4; j++) {
            int col = bn + tx * 4 + j;
            float v = c[i][j];
            if (Res) v += Res[(size_t)row * N + col];
            C[(size_t)row * N + col] = v;
        }
    }
}

// ----------------------------------------------------------------------------
// RoPE (rotate-half), in-place. Angles computed in double to dodge fast-math
// sin/cos range-reduction error at pos up to 2047.
// ----------------------------------------------------------------------------
__global__ void rope_kernel(float* __restrict__ x, int H, int stride, int total) {
    int idx = blockIdx.x * blockDim.x + threadIdx.x;
    if (idx >= total) return;
    const int i = idx & 31;                // dim pair index 0..31
    const int h = (idx >> 5) % H;
    const int s = idx / (32 * H);
    const double inv = pow(10000.0, -(double)(2 * i) / (double)HD);
    const double ang = (double)s * inv;
    const float cs = (float)cos(ang);
    const float sn = (float)sin(ang);
    float* p = x + (size_t)s * stride + h * HD;
    const float x1 = p[i], x2 = p[i + 32];
    p[i]      = x1 * cs - x2 * sn;
    p[i + 32] = x1 * sn + x2 * cs;
}

// ----------------------------------------------------------------------------
// Causal GQA flash attention.
// Grid: (HQ, S/64). Block: 128 threads = 2 threads per query row; each thread
// owns 32 of the 64 head dims. Score dot combined via shfl_xor(1).
// ----------------------------------------------------------------------------
__global__ __launch_bounds__(128) void attn_kernel(
    const float* __restrict__ Q, const float* __restrict__ K,
    const float* __restrict__ V, float* __restrict__ O) {
    const int h    = blockIdx.x;        // query head
    const int qt   = blockIdx.y;        // query tile (64 rows)
    const int t    = threadIdx.x;
    const int row  = t >> 1;            // 0..63 within tile
    const int half = t & 1;             // which 32 dims
    const int s    = qt * 64 + row;
    const int kvh  = h >> 2;            // GROUP=4
    const float scale = 0.125f;         // 1/sqrt(64)

    __shared__ float Ks[64][64];
    __shared__ float Vs[64][64];

    float qr[32];
    const float* qptr = Q + (size_t)s * DMODEL + h * HD + half * 32;
    #pragma unroll
    for (int i = 0; i < 32; i++) qr[i] = qptr[i] * scale;

    float acc[32];
    #pragma unroll
    for (int i = 0; i < 32; i++) acc[i] = 0.f;
    float m = -1e30f, l = 0.f;

    for (int kt = 0; kt <= qt; kt++) {
        __syncthreads();
        for (int idx = t; idx < 64 * 64; idx += 128) {
            int r = idx >> 6, c = idx & 63;
            size_t gsrc = (size_t)(kt * 64 + r) * KV_DIM + kvh * HD + c;
            Ks[r][c] = K[gsrc];
            Vs[r][c] = V[gsrc];
        }
        __syncthreads();
        const int jmax = (kt == qt) ? (row + 1) : 64;
        for (int j = 0; j < jmax; j++) {
            float p = 0.f;
            #pragma unroll
            for (int i = 0; i < 32; i++) p = fmaf(qr[i], Ks[j][half * 32 + i], p);
            p += __shfl_xor_sync(0xffffffffu, p, 1);
            float mnew  = fmaxf(m, p);
            float alpha = __expf(m - mnew);
            float e     = __expf(p - mnew);
            l = l * alpha + e;
            m = mnew;
            #pragma unroll
            for (int i = 0; i < 32; i++)
                acc[i] = fmaf(acc[i], alpha, e * Vs[j][half * 32 + i]);
        }
    }
    const float inv = 1.f / l;
    float* optr = O + (size_t)s * DMODEL + h * HD + half * 32;
    #pragma unroll
    for (int i = 0; i < 32; i++) optr[i] = acc[i] * inv;
}

// ----------------------------------------------------------------------------
// Launch
// ----------------------------------------------------------------------------
extern "C" void kernel_launch(void* const* d_in, const int* in_sizes, int n_in,
                              void* d_out, int out_size) {
    const float* x  = (const float*)d_in[0];
    const float* g  = (const float*)d_in[1];
    const float* wq = (const float*)d_in[2];
    const float* wk = (const float*)d_in[3];
    const float* wv = (const float*)d_in[4];
    const float* wo = (const float*)d_in[5];
    float* out = (float*)d_out;

    static float *ph = nullptr, *pq = nullptr, *pk = nullptr, *pv = nullptr, *po = nullptr;
    if (!ph) {
        cudaGetSymbolAddress((void**)&ph, g_h);
        cudaGetSymbolAddress((void**)&pq, g_q);
        cudaGetSymbolAddress((void**)&pk, g_k);
        cudaGetSymbolAddress((void**)&pv, g_v);
        cudaGetSymbolAddress((void**)&po, g_o);
    }

    rmsnorm_kernel<<<S_LEN, 256>>>(x, g, ph);

    gemm_kernel<<<dim3(DMODEL / 64, S_LEN / 64), 256>>>(ph, wq, nullptr, pq, S_LEN, DMODEL, DMODEL);
    gemm_kernel<<<dim3(KV_DIM / 64, S_LEN / 64), 256>>>(ph, wk, nullptr, pk, S_LEN, KV_DIM, DMODEL);
    gemm_kernel<<<dim3(KV_DIM / 64, S_LEN / 64), 256>>>(ph, wv, nullptr, pv, S_LEN, KV_DIM, DMODEL);

    {
        int total_q = S_LEN * HQ * (HD / 2);
        rope_kernel<<<(total_q + 255) / 256, 256>>>(pq, HQ, DMODEL, total_q);
        int total_k = S_LEN * HKV * (HD / 2);
        rope_kernel<<<(total_k + 255) / 256, 256>>>(pk, HKV, KV_DIM, total_k);
    }

    attn_kernel<<<dim3(HQ, S_LEN / 64), 128>>>(pq, pk, pv, po);

    gemm_kernel<<<dim3(DMODEL / 64, S_LEN / 64), 256>>>(po, wo, x, out, S_LEN, DMODEL, DMODEL);
}

// round 3
// speedup vs baseline: 1.3196x; 1.3196x over previous
#include <cuda_runtime.h>
#include <cuda_bf16.h>
#include <cstdint>
#include <math.h>

// ----------------------------------------------------------------------------
// Problem constants
// ----------------------------------------------------------------------------
#define S_LEN   2048
#define DMODEL  2048
#define HQ      32
#define HKV     8
#define HD      64
#define KV_DIM  (HKV*HD)   // 512

typedef __nv_bfloat16 bf16;

// ----------------------------------------------------------------------------
// Scratch (static __device__ arrays: allocation-free)
// ----------------------------------------------------------------------------
__device__ bf16  g_hh[S_LEN * DMODEL],  g_hl[S_LEN * DMODEL];     // rmsnorm out, split
__device__ bf16  g_wqh[DMODEL * DMODEL], g_wql[DMODEL * DMODEL];  // wq^T split [N,K]
__device__ bf16  g_wkh[KV_DIM * DMODEL], g_wkl[KV_DIM * DMODEL];
__device__ bf16  g_wvh[KV_DIM * DMODEL], g_wvl[KV_DIM * DMODEL];
__device__ bf16  g_woh[DMODEL * DMODEL], g_wol[DMODEL * DMODEL];
__device__ bf16  g_ohh[S_LEN * DMODEL],  g_ohl[S_LEN * DMODEL];   // attn out, split
__device__ float g_q[S_LEN * DMODEL];
__device__ float g_k[S_LEN * KV_DIM];
__device__ float g_v[S_LEN * KV_DIM];
__device__ float g_o[S_LEN * DMODEL];

// ----------------------------------------------------------------------------
// mma.sync helper (sm_80+ HMMA, legal on compute_103 base target)
// ----------------------------------------------------------------------------
__device__ __forceinline__ void mma16816(float* c, const uint32_t* a,
                                         uint32_t b0, uint32_t b1) {
    asm volatile(
        "mma.sync.aligned.m16n8k16.row.col.f32.bf16.bf16.f32 "
        "{%0,%1,%2,%3}, {%4,%5,%6,%7}, {%8,%9}, {%0,%1,%2,%3};"
        : "+f"(c[0]), "+f"(c[1]), "+f"(c[2]), "+f"(c[3])
        : "r"(a[0]), "r"(a[1]), "r"(a[2]), "r"(a[3]), "r"(b0), "r"(b1));
}

// ----------------------------------------------------------------------------
// RMSNorm: one block per row; writes bf16 hi/lo split directly
// ----------------------------------------------------------------------------
__global__ void rmsnorm_kernel(const float* __restrict__ x,
                               const float* __restrict__ g,
                               bf16* __restrict__ hh, bf16* __restrict__ hl) {
    const int s = blockIdx.x;
    const float* xr = x + (size_t)s * DMODEL;
    float sum = 0.f;
    for (int d = threadIdx.x; d < DMODEL; d += 256) {
        float v = xr[d];
        sum += v * v;
    }
    __shared__ float red[8];
    #pragma unroll
    for (int o = 16; o > 0; o >>= 1) sum += __shfl_xor_sync(0xffffffffu, sum, o);
    if ((threadIdx.x & 31) == 0) red[threadIdx.x >> 5] = sum;
    __syncthreads();
    if (threadIdx.x < 32) {
        float v = (threadIdx.x < 8) ? red[threadIdx.x] : 0.f;
        #pragma unroll
        for (int o = 4; o > 0; o >>= 1) v += __shfl_xor_sync(0xffffffffu, v, o);
        if (threadIdx.x == 0) red[0] = v;
    }
    __syncthreads();
    const float rinv = rsqrtf(red[0] / (float)DMODEL + 1e-9f);
    for (int d = threadIdx.x; d < DMODEL; d += 256) {
        float v = xr[d] * rinv * g[d];
        bf16 h = __float2bfloat16(v);
        hh[(size_t)s * DMODEL + d] = h;
        hl[(size_t)s * DMODEL + d] = __float2bfloat16(v - __bfloat162float(h));
    }
}

// ----------------------------------------------------------------------------
// Transpose + bf16 split: W[K,N] (fp32) -> Wt_hi/lo[N,K] (bf16)
// ----------------------------------------------------------------------------
__global__ void transpose_split_kernel(const float* __restrict__ w,
                                       bf16* __restrict__ th, bf16* __restrict__ tl,
                                       int K, int N) {
    __shared__ float t[32][33];
    const int n0 = blockIdx.x * 32, k0 = blockIdx.y * 32;
    const int tx = threadIdx.x, ty = threadIdx.y;  // (32, 8)
    #pragma unroll
    for (int i = 0; i < 32; i += 8)
        t[ty + i][tx] = w[(size_t)(k0 + ty + i) * N + n0 + tx];
    __syncthreads();
    #pragma unroll
    for (int i = 0; i < 32; i += 8) {
        float v = t[tx][ty + i];
        bf16 h = __float2bfloat16(v);
        size_t o = (size_t)(n0 + ty + i) * K + k0 + tx;
        th[o] = h;
        tl[o] = __float2bfloat16(v - __bfloat162float(h));
    }
}

// ----------------------------------------------------------------------------
// Plain bf16 split (for attention output)
// ----------------------------------------------------------------------------
__global__ void split_kernel(const float* __restrict__ in,
                             bf16* __restrict__ hi, bf16* __restrict__ lo, int n) {
    int i = blockIdx.x * blockDim.x + threadIdx.x;
    if (i < n) {
        float v = in[i];
        bf16 h = __float2bfloat16(v);
        hi[i] = h;
        lo[i] = __float2bfloat16(v - __bfloat162float(h));
    }
}

// ----------------------------------------------------------------------------
// bf16x3 GEMM via mma.sync: C[M,N] = A @ B^T (+Res), fp32 accumulate.
// A (hi/lo): [M,K] bf16 row-major. B (hi/lo): [N,K] bf16 row-major.
// Block 128x128, BK=32, 256 threads = 8 warps (2M x 4N), warp tile 64x32.
// Smem rows padded to 40 halves (80B) -> conflict-free fragment loads.
// ----------------------------------------------------------------------------
#define KP 40   // padded row stride in halves

__global__ __launch_bounds__(256) void mma_gemm_kernel(
    const bf16* __restrict__ Ah, const bf16* __restrict__ Al,
    const bf16* __restrict__ Bh, const bf16* __restrict__ Bl,
    const float* __restrict__ Res, float* __restrict__ C,
    int N, int K) {
    __shared__ bf16 sAh[128 * KP], sAl[128 * KP];
    __shared__ bf16 sBh[128 * KP], sBl[128 * KP];

    const int tid  = threadIdx.x;
    const int lane = tid & 31, wid = tid >> 5;
    const int bm = blockIdx.y * 128, bn = blockIdx.x * 128;
    const int wmb = (wid & 1) * 64;   // warp M offset
    const int wnb = (wid >> 1) * 32;  // warp N offset
    const int lr = lane >> 2;         // lane row group 0..7
    const int lc = (lane & 3) * 2;    // lane k/col offset

    float acc[4][4][4];
    #pragma unroll
    for (int mt = 0; mt < 4; mt++)
        #pragma unroll
        for (int nt = 0; nt < 4; nt++)
            #pragma unroll
            for (int i = 0; i < 4; i++) acc[mt][nt][i] = 0.f;

    for (int k0 = 0; k0 < K; k0 += 32) {
        // Load 128x32 tiles (16B chunks); 512 chunks / 256 threads = 2 each
        #pragma unroll
        for (int p = 0; p < 2; p++) {
            const int idx = tid + p * 256;
            const int r = idx >> 2, c8 = (idx & 3) * 8;
            const int so = r * KP + c8;
            const size_t ga = (size_t)(bm + r) * K + k0 + c8;
            const size_t gb = (size_t)(bn + r) * K + k0 + c8;
            *(uint4*)(sAh + so) = *(const uint4*)(Ah + ga);
            *(uint4*)(sAl + so) = *(const uint4*)(Al + ga);
            *(uint4*)(sBh + so) = *(const uint4*)(Bh + gb);
            *(uint4*)(sBl + so) = *(const uint4*)(Bl + gb);
        }
        __syncthreads();

        #pragma unroll
        for (int kk = 0; kk < 32; kk += 16) {
            uint32_t fah[4][4], fal[4][4];
            #pragma unroll
            for (int mt = 0; mt < 4; mt++) {
                const int r0 = (wmb + mt * 16 + lr) * KP + kk + lc;
                const int r1 = r0 + 8 * KP;
                fah[mt][0] = *(const uint32_t*)(sAh + r0);
                fah[mt][1] = *(const uint32_t*)(sAh + r1);
                fah[mt][2] = *(const uint32_t*)(sAh + r0 + 8);
                fah[mt][3] = *(const uint32_t*)(sAh + r1 + 8);
                fal[mt][0] = *(const uint32_t*)(sAl + r0);
                fal[mt][1] = *(const uint32_t*)(sAl + r1);
                fal[mt][2] = *(const uint32_t*)(sAl + r0 + 8);
                fal[mt][3] = *(const uint32_t*)(sAl + r1 + 8);
            }
            #pragma unroll
            for (int nt = 0; nt < 4; nt++) {
                const int nb = (wnb + nt * 8 + lr) * KP + kk + lc;
                const uint32_t bh0 = *(const uint32_t*)(sBh + nb);
                const uint32_t bh1 = *(const uint32_t*)(sBh + nb + 8);
                const uint32_t bl0 = *(const uint32_t*)(sBl + nb);
                const uint32_t bl1 = *(const uint32_t*)(sBl + nb + 8);
                #pragma unroll
                for (int mt = 0; mt < 4; mt++) {
                    mma16816(acc[mt][nt], fah[mt], bh0, bh1);
                    mma16816(acc[mt][nt], fah[mt], bl0, bl1);
                    mma16816(acc[mt][nt], fal[mt], bh0, bh1);
                }
            }
        }
        __syncthreads();
    }

    // Epilogue: c0,c1 -> (row g, col lc..lc+1), c2,c3 -> (row g+8)
    #pragma unroll
    for (int mt = 0; mt < 4; mt++) {
        const int row0 = bm + wmb + mt * 16 + lr;
        #pragma unroll
        for (int nt = 0; nt < 4; nt++) {
            const int col = bn + wnb + nt * 8 + lc;
            float2 v0 = make_float2(acc[mt][nt][0], acc[mt][nt][1]);
            float2 v1 = make_float2(acc[mt][nt][2], acc[mt][nt][3]);
            if (Res) {
                const float2 r0 = *(const float2*)(Res + (size_t)row0 * N + col);
                const float2 r1 = *(const float2*)(Res + (size_t)(row0 + 8) * N + col);
                v0.x += r0.x; v0.y += r0.y;
                v1.x += r1.x; v1.y += r1.y;
            }
            *(float2*)(C + (size_t)row0 * N + col) = v0;
            *(float2*)(C + (size_t)(row0 + 8) * N + col) = v1;
        }
    }
}

// ----------------------------------------------------------------------------
// RoPE (rotate-half), in-place, angles in double (range-reduction safety)
// ----------------------------------------------------------------------------
__global__ void rope_kernel(float* __restrict__ x, int H, int stride, int total) {
    int idx = blockIdx.x * blockDim.x + threadIdx.x;
    if (idx >= total) return;
    const int i = idx & 31;
    const int h = (idx >> 5) % H;
    const int s = idx / (32 * H);
    const double inv = pow(10000.0, -(double)(2 * i) / (double)HD);
    const double ang = (double)s * inv;
    const float cs = (float)cos(ang);
    const float sn = (float)sin(ang);
    float* p = x + (size_t)s * stride + h * HD;
    const float x1 = p[i], x2 = p[i + 32];
    p[i]      = x1 * cs - x2 * sn;
    p[i + 32] = x1 * sn + x2 * cs;
}

// ----------------------------------------------------------------------------
// Causal GQA flash attention (fp32 SIMT). Grid: (HQ, S/64), 128 threads.
// ----------------------------------------------------------------------------
__global__ __launch_bounds__(128) void attn_kernel(
    const float* __restrict__ Q, const float* __restrict__ K,
    const float* __restrict__ V, float* __restrict__ O) {
    const int h    = blockIdx.x;
    const int qt   = blockIdx.y;
    const int t    = threadIdx.x;
    const int row  = t >> 1;
    const int half = t & 1;
    const int s    = qt * 64 + row;
    const int kvh  = h >> 2;
    const float scale = 0.125f;

    __shared__ float Ks[64][64];
    __shared__ float Vs[64][64];

    float qr[32];
    const float* qptr = Q + (size_t)s * DMODEL + h * HD + half * 32;
    #pragma unroll
    for (int i = 0; i < 32; i++) qr[i] = qptr[i] * scale;

    float acc[32];
    #pragma unroll
    for (int i = 0; i < 32; i++) acc[i] = 0.f;
    float m = -1e30f, l = 0.f;

    for (int kt = 0; kt <= qt; kt++) {
        __syncthreads();
        for (int idx = t; idx < 64 * 64; idx += 128) {
            int r = idx >> 6, c = idx & 63;
            size_t gsrc = (size_t)(kt * 64 + r) * KV_DIM + kvh * HD + c;
            Ks[r][c] = K[gsrc];
            Vs[r][c] = V[gsrc];
        }
        __syncthreads();
        const int jmax = (kt == qt) ? (row + 1) : 64;
        for (int j = 0; j < jmax; j++) {
            float p = 0.f;
            #pragma unroll
            for (int i = 0; i < 32; i++) p = fmaf(qr[i], Ks[j][half * 32 + i], p);
            p += __shfl_xor_sync(0xffffffffu, p, 1);
            float mnew  = fmaxf(m, p);
            float alpha = __expf(m - mnew);
            float e     = __expf(p - mnew);
            l = l * alpha + e;
            m = mnew;
            #pragma unroll
            for (int i = 0; i < 32; i++)
                acc[i] = fmaf(acc[i], alpha, e * Vs[j][half * 32 + i]);
        }
    }
    const float inv = 1.f / l;
    float* optr = O + (size_t)s * DMODEL + h * HD + half * 32;
    #pragma unroll
    for (int i = 0; i < 32; i++) optr[i] = acc[i] * inv;
}

// ----------------------------------------------------------------------------
// Launch
// ----------------------------------------------------------------------------
extern "C" void kernel_launch(void* const* d_in, const int* in_sizes, int n_in,
                              void* d_out, int out_size) {
    const float* x  = (const float*)d_in[0];
    const float* g  = (const float*)d_in[1];
    const float* wq = (const float*)d_in[2];
    const float* wk = (const float*)d_in[3];
    const float* wv = (const float*)d_in[4];
    const float* wo = (const float*)d_in[5];
    float* out = (float*)d_out;

    static bool inited = false;
    static bf16 *hh, *hl, *wqh, *wql, *wkh, *wkl, *wvh, *wvl, *woh, *wol, *ohh, *ohl;
    static float *pq, *pk, *pv, *po;
    if (!inited) {
        inited = true;
        cudaGetSymbolAddress((void**)&hh,  g_hh);
        cudaGetSymbolAddress((void**)&hl,  g_hl);
        cudaGetSymbolAddress((void**)&wqh, g_wqh);
        cudaGetSymbolAddress((void**)&wql, g_wql);
        cudaGetSymbolAddress((void**)&wkh, g_wkh);
        cudaGetSymbolAddress((void**)&wkl, g_wkl);
        cudaGetSymbolAddress((void**)&wvh, g_wvh);
        cudaGetSymbolAddress((void**)&wvl, g_wvl);
        cudaGetSymbolAddress((void**)&woh, g_woh);
        cudaGetSymbolAddress((void**)&wol, g_wol);
        cudaGetSymbolAddress((void**)&ohh, g_ohh);
        cudaGetSymbolAddress((void**)&ohl, g_ohl);
        cudaGetSymbolAddress((void**)&pq,  g_q);
        cudaGetSymbolAddress((void**)&pk,  g_k);
        cudaGetSymbolAddress((void**)&pv,  g_v);
        cudaGetSymbolAddress((void**)&po,  g_o);
    }

    // 1) RMSNorm -> bf16 split
    rmsnorm_kernel<<<S_LEN, 256>>>(x, g, hh, hl);

    // 2) Weight transpose + split
    dim3 tb(32, 8);
    transpose_split_kernel<<<dim3(DMODEL / 32, DMODEL / 32), tb>>>(wq, wqh, wql, DMODEL, DMODEL);
    transpose_split_kernel<<<dim3(KV_DIM / 32, DMODEL / 32), tb>>>(wk, wkh, wkl, DMODEL, KV_DIM);
    transpose_split_kernel<<<dim3(KV_DIM / 32, DMODEL / 32), tb>>>(wv, wvh, wvl, DMODEL, KV_DIM);
    transpose_split_kernel<<<dim3(DMODEL / 32, DMODEL / 32), tb>>>(wo, woh, wol, DMODEL, DMODEL);

    // 3) Projections on tensor cores (bf16x3 via mma.sync)
    mma_gemm_kernel<<<dim3(DMODEL / 128, S_LEN / 128), 256>>>(
        hh, hl, wqh, wql, nullptr, pq, DMODEL, DMODEL);
    mma_gemm_kernel<<<dim3(KV_DIM / 128, S_LEN / 128), 256>>>(
        hh, hl, wkh, wkl, nullptr, pk, KV_DIM, DMODEL);
    mma_gemm_kernel<<<dim3(KV_DIM / 128, S_LEN / 128), 256>>>(
        hh, hl, wvh, wvl, nullptr, pv, KV_DIM, DMODEL);

    // 4) RoPE
    {
        int total_q = S_LEN * HQ * (HD / 2);
        rope_kernel<<<(total_q + 255) / 256, 256>>>(pq, HQ, DMODEL, total_q);
        int total_k = S_LEN * HKV * (HD / 2);
        rope_kernel<<<(total_k + 255) / 256, 256>>>(pk, HKV, KV_DIM, total_k);
    }

    // 5) Attention
    attn_kernel<<<dim3(HQ, S_LEN / 64), 128>>>(pq, pk, pv, po);

    // 6) Output projection + residual on tensor cores
    split_kernel<<<(S_LEN * DMODEL + 255) / 256, 256>>>(po, ohh, ohl, S_LEN * DMODEL);
    mma_gemm_kernel<<<dim3(DMODEL / 128, S_LEN / 128), 256>>>(
        ohh, ohl, woh, wol, x, out, DMODEL, DMODEL);
}

// round 4
// speedup vs baseline: 2.5697x; 1.9473x over previous
#include <cuda_runtime.h>
#include <cuda_bf16.h>
#include <cstdint>
#include <math.h>

// ----------------------------------------------------------------------------
// Problem constants
// ----------------------------------------------------------------------------
#define S_LEN   2048
#define DMODEL  2048
#define HQ      32
#define HKV     8
#define HD      64
#define KV_DIM  (HKV*HD)   // 512

typedef __nv_bfloat16 bf16;

// ----------------------------------------------------------------------------
// Scratch (static __device__ arrays: allocation-free)
// ----------------------------------------------------------------------------
__device__ bf16  g_hh[S_LEN * DMODEL],  g_hl[S_LEN * DMODEL];       // rmsnorm out (split)
__device__ bf16  g_wqh[DMODEL * DMODEL], g_wql[DMODEL * DMODEL];    // wq^T split [N,K]
__device__ bf16  g_kvh[2 * KV_DIM * DMODEL], g_kvl[2 * KV_DIM * DMODEL]; // [wk^T; wv^T]
__device__ bf16  g_woh[DMODEL * DMODEL], g_wol[DMODEL * DMODEL];
__device__ float g_pq[S_LEN * DMODEL];         // q proj (pre-rope)
__device__ float g_pkv[S_LEN * 2 * KV_DIM];    // k|v proj  [S][1024]
__device__ bf16  g_qh[S_LEN * DMODEL],  g_ql[S_LEN * DMODEL];       // roped+scaled q (split)
__device__ bf16  g_kh[S_LEN * KV_DIM],  g_kl[S_LEN * KV_DIM];       // roped k (split)
__device__ bf16  g_vh[S_LEN * KV_DIM],  g_vl[S_LEN * KV_DIM];       // v (split)
__device__ bf16  g_oh[S_LEN * DMODEL],  g_ol[S_LEN * DMODEL];       // attn out (split)

// ----------------------------------------------------------------------------
// PTX helpers (sm_80+ features only — legal on plain compute_103)
// ----------------------------------------------------------------------------
__device__ __forceinline__ void mma16816(float* c, const uint32_t* a,
                                         uint32_t b0, uint32_t b1) {
    asm volatile(
        "mma.sync.aligned.m16n8k16.row.col.f32.bf16.bf16.f32 "
        "{%0,%1,%2,%3}, {%4,%5,%6,%7}, {%8,%9}, {%0,%1,%2,%3};"
        : "+f"(c[0]), "+f"(c[1]), "+f"(c[2]), "+f"(c[3])
        : "r"(a[0]), "r"(a[1]), "r"(a[2]), "r"(a[3]), "r"(b0), "r"(b1));
}
__device__ __forceinline__ void ldsm4(uint32_t* r, uint32_t addr) {
    asm volatile("ldmatrix.sync.aligned.m8n8.x4.shared.b16 {%0,%1,%2,%3}, [%4];"
                 : "=r"(r[0]), "=r"(r[1]), "=r"(r[2]), "=r"(r[3]) : "r"(addr));
}
__device__ __forceinline__ void cp16(uint32_t saddr, const void* g) {
    asm volatile("cp.async.cg.shared.global [%0], [%1], 16;" :: "r"(saddr), "l"(g));
}
__device__ __forceinline__ void cp_commit() {
    asm volatile("cp.async.commit_group;" ::: "memory");
}
__device__ __forceinline__ uint32_t scvta(const void* p) {
    return (uint32_t)__cvta_generic_to_shared(p);
}

// ----------------------------------------------------------------------------
// RMSNorm: one block per row; writes bf16 hi/lo split
// ----------------------------------------------------------------------------
__global__ void rmsnorm_kernel(const float* __restrict__ x,
                               const float* __restrict__ g,
                               bf16* __restrict__ hh, bf16* __restrict__ hl) {
    const int s = blockIdx.x;
    const float* xr = x + (size_t)s * DMODEL;
    float sum = 0.f;
    for (int d = threadIdx.x; d < DMODEL; d += 256) {
        float v = xr[d];
        sum += v * v;
    }
    __shared__ float red[8];
    #pragma unroll
    for (int o = 16; o > 0; o >>= 1) sum += __shfl_xor_sync(0xffffffffu, sum, o);
    if ((threadIdx.x & 31) == 0) red[threadIdx.x >> 5] = sum;
    __syncthreads();
    if (threadIdx.x < 32) {
        float v = (threadIdx.x < 8) ? red[threadIdx.x] : 0.f;
        #pragma unroll
        for (int o = 4; o > 0; o >>= 1) v += __shfl_xor_sync(0xffffffffu, v, o);
        if (threadIdx.x == 0) red[0] = v;
    }
    __syncthreads();
    const float rinv = rsqrtf(red[0] / (float)DMODEL + 1e-9f);
    for (int d = threadIdx.x; d < DMODEL; d += 256) {
        float v = xr[d] * rinv * g[d];
        bf16 h = __float2bfloat16(v);
        hh[(size_t)s * DMODEL + d] = h;
        hl[(size_t)s * DMODEL + d] = __float2bfloat16(v - __bfloat162float(h));
    }
}

// ----------------------------------------------------------------------------
// Transpose + bf16 split: W[K,N] fp32 -> Wt hi/lo [N,K] bf16
// ----------------------------------------------------------------------------
__global__ void transpose_split_kernel(const float* __restrict__ w,
                                       bf16* __restrict__ th, bf16* __restrict__ tl,
                                       int K, int N) {
    __shared__ float t[32][33];
    const int n0 = blockIdx.x * 32, k0 = blockIdx.y * 32;
    const int tx = threadIdx.x, ty = threadIdx.y;  // (32, 8)
    #pragma unroll
    for (int i = 0; i < 32; i += 8)
        t[ty + i][tx] = w[(size_t)(k0 + ty + i) * N + n0 + tx];
    __syncthreads();
    #pragma unroll
    for (int i = 0; i < 32; i += 8) {
        float v = t[tx][ty + i];
        bf16 h = __float2bfloat16(v);
        size_t o = (size_t)(n0 + ty + i) * K + k0 + tx;
        th[o] = h;
        tl[o] = __float2bfloat16(v - __bfloat162float(h));
    }
}

// ----------------------------------------------------------------------------
// bf16x3 GEMM v2: cp.async double-buffered + ldmatrix.
// C[M,N] = A @ B^T (+Res). Block 128x128, BK=32, 256 thr = 8 warps (2Mx4N).
// Dynamic smem: 4 operand arrays x 2 stages x (128x40 bf16).
// ----------------------------------------------------------------------------
#define KP 40                      // padded row stride (halves)
#define STG 10240                  // bytes per array per stage (128*40*2)
#define GEMM_SMEM (8 * STG)        // 81920

__global__ __launch_bounds__(256) void mma_gemm_kernel(
    const bf16* __restrict__ Ah, const bf16* __restrict__ Al,
    const bf16* __restrict__ Bh, const bf16* __restrict__ Bl,
    const float* __restrict__ Res, float* __restrict__ C,
    int N, int K) {
    extern __shared__ __align__(16) char sm[];
    // offsets: AH stage s -> s*STG ; AL -> 2*STG + s*STG ; BH -> 4*STG + ... ; BL -> 6*STG + ...
    const int tid  = threadIdx.x;
    const int lane = tid & 31, wid = tid >> 5;
    const int bm = blockIdx.y * 128, bn = blockIdx.x * 128;
    const int wmb = (wid & 1) * 64;
    const int wnb = (wid >> 1) * 32;
    const int lr = lane >> 2, lc = (lane & 3) * 2;
    const uint32_t smb = scvta(sm);

    float acc[4][4][4];
    #pragma unroll
    for (int mt = 0; mt < 4; mt++)
        #pragma unroll
        for (int nt = 0; nt < 4; nt++)
            #pragma unroll
            for (int i = 0; i < 4; i++) acc[mt][nt][i] = 0.f;

    // per-thread load coords (2 chunks of 16B per array per stage)
    const int r0c = tid >> 2,            c0c = (tid & 3) * 8;
    const int r1c = (tid + 256) >> 2,    c1c = ((tid + 256) & 3) * 8;

    auto load_stage = [&](int s, int kc) {
        const uint32_t o0 = (uint32_t)(r0c * KP + c0c) * 2;
        const uint32_t o1 = (uint32_t)(r1c * KP + c1c) * 2;
        const size_t ga0 = (size_t)(bm + r0c) * K + kc + c0c;
        const size_t ga1 = (size_t)(bm + r1c) * K + kc + c1c;
        const size_t gb0 = (size_t)(bn + r0c) * K + kc + c0c;
        const size_t gb1 = (size_t)(bn + r1c) * K + kc + c1c;
        const uint32_t ss = (uint32_t)(s * STG);
        cp16(smb + ss + o0,            Ah + ga0);
        cp16(smb + ss + o1,            Ah + ga1);
        cp16(smb + 2*STG + ss + o0,    Al + ga0);
        cp16(smb + 2*STG + ss + o1,    Al + ga1);
        cp16(smb + 4*STG + ss + o0,    Bh + gb0);
        cp16(smb + 4*STG + ss + o1,    Bh + gb1);
        cp16(smb + 6*STG + ss + o0,    Bl + gb0);
        cp16(smb + 6*STG + ss + o1,    Bl + gb1);
    };

    const int nch = K >> 5;
    load_stage(0, 0);
    cp_commit();

    // A-frag lane addressing pattern
    const int a_row = lane & 15;
    const int a_kof = (lane >> 4) << 3;
    // B-frag lane addressing pattern (x4 covers 2 n-tiles)
    const int b_row = (lane & 7) + ((lane >> 4) << 3);
    const int b_kof = ((lane >> 3) & 1) << 3;

    for (int c = 0; c < nch; c++) {
        const int cur = c & 1;
        if (c + 1 < nch) {
            load_stage((c + 1) & 1, (c + 1) * 32);
            cp_commit();
            asm volatile("cp.async.wait_group 1;" ::: "memory");
        } else {
            asm volatile("cp.async.wait_group 0;" ::: "memory");
        }
        __syncthreads();

        const uint32_t sAh = smb + (uint32_t)(cur * STG);
        const uint32_t sAl = sAh + 2 * STG;
        const uint32_t sBh = sAh + 4 * STG;
        const uint32_t sBl = sAh + 6 * STG;

        #pragma unroll
        for (int kk = 0; kk < 32; kk += 16) {
            uint32_t fah[4][4], fal[4][4];
            #pragma unroll
            for (int mt = 0; mt < 4; mt++) {
                const uint32_t off = (uint32_t)((wmb + mt * 16 + a_row) * KP + kk + a_kof) * 2;
                ldsm4(fah[mt], sAh + off);
                ldsm4(fal[mt], sAl + off);
            }
            #pragma unroll
            for (int p2 = 0; p2 < 2; p2++) {   // each covers 2 n-tiles
                const uint32_t off = (uint32_t)((wnb + p2 * 16 + b_row) * KP + kk + b_kof) * 2;
                uint32_t rh[4], rl[4];
                ldsm4(rh, sBh + off);
                ldsm4(rl, sBl + off);
                #pragma unroll
                for (int mt = 0; mt < 4; mt++) {
                    mma16816(acc[mt][2 * p2],     fah[mt], rh[0], rh[1]);
                    mma16816(acc[mt][2 * p2],     fah[mt], rl[0], rl[1]);
                    mma16816(acc[mt][2 * p2],     fal[mt], rh[0], rh[1]);
                    mma16816(acc[mt][2 * p2 + 1], fah[mt], rh[2], rh[3]);
                    mma16816(acc[mt][2 * p2 + 1], fah[mt], rl[2], rl[3]);
                    mma16816(acc[mt][2 * p2 + 1], fal[mt], rh[2], rh[3]);
                }
            }
        }
        __syncthreads();
    }

    #pragma unroll
    for (int mt = 0; mt < 4; mt++) {
        const int row0 = bm + wmb + mt * 16 + lr;
        #pragma unroll
        for (int nt = 0; nt < 4; nt++) {
            const int col = bn + wnb + nt * 8 + lc;
            float2 v0 = make_float2(acc[mt][nt][0], acc[mt][nt][1]);
            float2 v1 = make_float2(acc[mt][nt][2], acc[mt][nt][3]);
            if (Res) {
                const float2 q0 = *(const float2*)(Res + (size_t)row0 * N + col);
                const float2 q1 = *(const float2*)(Res + (size_t)(row0 + 8) * N + col);
                v0.x += q0.x; v0.y += q0.y;
                v1.x += q1.x; v1.y += q1.y;
            }
            *(float2*)(C + (size_t)row0 * N + col) = v0;
            *(float2*)(C + (size_t)(row0 + 8) * N + col) = v1;
        }
    }
}

// ----------------------------------------------------------------------------
// RoPE + scale + bf16 split. Reads fp32 proj, writes bf16 hi/lo.
// ----------------------------------------------------------------------------
__global__ void rope_split_kernel(const float* __restrict__ src, int src_stride,
                                  bf16* __restrict__ oh, bf16* __restrict__ ol,
                                  int o_stride, int H, float scale, int total) {
    int idx = blockIdx.x * blockDim.x + threadIdx.x;
    if (idx >= total) return;
    const int i = idx & 31;
    const int h = (idx >> 5) % H;
    const int s = idx / (32 * H);
    const double inv = pow(10000.0, -(double)(2 * i) / (double)HD);
    const double ang = (double)s * inv;
    const float cs = (float)cos(ang);
    const float sn = (float)sin(ang);
    const float* p = src + (size_t)s * src_stride + h * HD;
    const float x1 = p[i], x2 = p[i + 32];
    const float y1 = (x1 * cs - x2 * sn) * scale;
    const float y2 = (x1 * sn + x2 * cs) * scale;
    bf16* ph = oh + (size_t)s * o_stride + h * HD;
    bf16* pl = ol + (size_t)s * o_stride + h * HD;
    bf16 b1 = __float2bfloat16(y1), b2 = __float2bfloat16(y2);
    ph[i] = b1;        ph[i + 32] = b2;
    pl[i] = __float2bfloat16(y1 - __bfloat162float(b1));
    pl[i + 32] = __float2bfloat16(y2 - __bfloat162float(b2));
}

// ----------------------------------------------------------------------------
// Strided bf16 split for V: src [S][1024] cols 512..1023 -> vh/vl [S][512]
// ----------------------------------------------------------------------------
__global__ void split_v_kernel(const float* __restrict__ src,
                               bf16* __restrict__ hi, bf16* __restrict__ lo) {
    int i = blockIdx.x * blockDim.x + threadIdx.x;
    if (i >= S_LEN * KV_DIM) return;
    const int s = i >> 9, c = i & 511;
    const float v = src[(size_t)s * (2 * KV_DIM) + KV_DIM + c];
    bf16 h = __float2bfloat16(v);
    hi[i] = h;
    lo[i] = __float2bfloat16(v - __bfloat162float(h));
}

// ----------------------------------------------------------------------------
// Tensor-core causal GQA flash attention (bf16x3 split precision).
// Grid (HQ, S/128). 256 threads = 8 warps x 16 q-rows. KV tiles of 64.
// Writes O as bf16 hi/lo split directly.
// ----------------------------------------------------------------------------
#define AQP 72   // padded row stride (halves) for attn smem tiles

__global__ __launch_bounds__(256) void attn_mma_kernel(
    const bf16* __restrict__ qh, const bf16* __restrict__ ql,
    const bf16* __restrict__ kh, const bf16* __restrict__ kl,
    const bf16* __restrict__ vh, const bf16* __restrict__ vl,
    bf16* __restrict__ oh, bf16* __restrict__ ol) {
    __shared__ __align__(16) char sbuf[36864];
    bf16* QH = (bf16*)sbuf;                 // [128][72]
    bf16* QL = (bf16*)(sbuf + 18432);
    bf16* KH = (bf16*)sbuf;                 // [64][72] (reused after Q frags)
    bf16* KL = (bf16*)(sbuf + 9216);
    bf16* VH = (bf16*)(sbuf + 18432);       // transposed: [d][kv]
    bf16* VL = (bf16*)(sbuf + 27648);

    const int h = blockIdx.x, qt = blockIdx.y;
    const int kvh = h >> 2;
    const int tid = threadIdx.x, lane = tid & 31, wid = tid >> 5;
    const int lr = lane >> 2, lc = (lane & 3) * 2;

    // ---- stage Q tile (already roped+scaled+split) ----
    #pragma unroll
    for (int p = 0; p < 4; p++) {
        const int idx = tid + p * 256;          // 1024 chunks of 8 halves
        const int r = idx >> 3, c8 = (idx & 7) * 8;
        const size_t go = (size_t)(qt * 128 + r) * DMODEL + h * HD + c8;
        *(uint4*)(QH + r * AQP + c8) = *(const uint4*)(qh + go);
        *(uint4*)(QL + r * AQP + c8) = *(const uint4*)(ql + go);
    }
    __syncthreads();

    // ---- Q fragments to registers ----
    uint32_t qfh[4][4], qfl[4][4];
    {
        const int a_row = lane & 15;
        const int a_kof = (lane >> 4) << 3;
        #pragma unroll
        for (int ks = 0; ks < 4; ks++) {
            const uint32_t off = (uint32_t)((wid * 16 + a_row) * AQP + ks * 16 + a_kof) * 2;
            ldsm4(qfh[ks], scvta(QH) + off);
            ldsm4(qfl[ks], scvta(QL) + off);
        }
    }
    __syncthreads();   // smem about to be reused for K/V

    float o[8][4];
    #pragma unroll
    for (int n = 0; n < 8; n++)
        #pragma unroll
        for (int i = 0; i < 4; i++) o[n][i] = 0.f;
    float m0 = -1e30f, m1 = -1e30f, l0 = 0.f, l1 = 0.f;

    const int row0g = qt * 128 + wid * 16 + lr;
    const int row1g = row0g + 8;
    const int nkt = 2 * qt + 2;

    const int b_row = (lane & 7) + ((lane >> 4) << 3);
    const int b_kof = ((lane >> 3) & 1) << 3;

    for (int kt = 0; kt < nkt; kt++) {
        // ---- load K tile [64 kv][64 d] ----
        #pragma unroll
        for (int p = 0; p < 2; p++) {
            const int idx = tid + p * 256;      // 512 chunks
            const int r = idx >> 3, c8 = (idx & 7) * 8;
            const size_t go = (size_t)(kt * 64 + r) * KV_DIM + kvh * HD + c8;
            *(uint4*)(KH + r * AQP + c8) = *(const uint4*)(kh + go);
            *(uint4*)(KL + r * AQP + c8) = *(const uint4*)(kl + go);
        }
        // ---- load V tile transposed: VH[d][kv] ----
        #pragma unroll
        for (int p = 0; p < 2; p++) {
            const int idx = tid + p * 256;
            const int r = idx >> 3, c8 = (idx & 7) * 8;
            const size_t go = (size_t)(kt * 64 + r) * KV_DIM + kvh * HD + c8;
            const uint4 a = *(const uint4*)(vh + go);
            const uint4 b = *(const uint4*)(vl + go);
            const bf16* ta = (const bf16*)&a;
            const bf16* tb = (const bf16*)&b;
            #pragma unroll
            for (int i = 0; i < 8; i++) {
                VH[(c8 + i) * AQP + r] = ta[i];
                VL[(c8 + i) * AQP + r] = tb[i];
            }
        }
        __syncthreads();

        // ---- S = Q K^T (scale folded into Q) ----
        float s[8][4];
        #pragma unroll
        for (int n = 0; n < 8; n++)
            #pragma unroll
            for (int i = 0; i < 4; i++) s[n][i] = 0.f;
        #pragma unroll
        for (int ks = 0; ks < 4; ks++) {
            #pragma unroll
            for (int p2 = 0; p2 < 4; p2++) {     // covers n-tiles 2p2, 2p2+1
                const uint32_t off = (uint32_t)((p2 * 16 + b_row) * AQP + ks * 16 + b_kof) * 2;
                uint32_t rh[4], rl[4];
                ldsm4(rh, scvta(KH) + off);
                ldsm4(rl, scvta(KL) + off);
                mma16816(s[2 * p2],     qfh[ks], rh[0], rh[1]);
                mma16816(s[2 * p2],     qfh[ks], rl[0], rl[1]);
                mma16816(s[2 * p2],     qfl[ks], rh[0], rh[1]);
                mma16816(s[2 * p2 + 1], qfh[ks], rh[2], rh[3]);
                mma16816(s[2 * p2 + 1], qfh[ks], rl[2], rl[3]);
                mma16816(s[2 * p2 + 1], qfl[ks], rh[2], rh[3]);
            }
        }

        // ---- causal mask (only last two tiles can cross the diagonal) ----
        if (kt >= 2 * qt) {
            #pragma unroll
            for (int n = 0; n < 8; n++) {
                const int colb = kt * 64 + n * 8 + lc;
                if (colb     > row0g) s[n][0] = -1e30f;
                if (colb + 1 > row0g) s[n][1] = -1e30f;
                if (colb     > row1g) s[n][2] = -1e30f;
                if (colb + 1 > row1g) s[n][3] = -1e30f;
            }
        }

        // ---- online softmax ----
        float tm0 = -1e30f, tm1 = -1e30f;
        #pragma unroll
        for (int n = 0; n < 8; n++) {
            tm0 = fmaxf(tm0, fmaxf(s[n][0], s[n][1]));
            tm1 = fmaxf(tm1, fmaxf(s[n][2], s[n][3]));
        }
        tm0 = fmaxf(tm0, __shfl_xor_sync(0xffffffffu, tm0, 1));
        tm0 = fmaxf(tm0, __shfl_xor_sync(0xffffffffu, tm0, 2));
        tm1 = fmaxf(tm1, __shfl_xor_sync(0xffffffffu, tm1, 1));
        tm1 = fmaxf(tm1, __shfl_xor_sync(0xffffffffu, tm1, 2));
        const float mn0 = fmaxf(m0, tm0), mn1 = fmaxf(m1, tm1);
        const float a0 = __expf(m0 - mn0), a1 = __expf(m1 - mn1);
        m0 = mn0; m1 = mn1;

        uint32_t pA[8], pB[8], pAl[8], pBl[8];  // packed bf16x2: (c0,c1) and (c2,c3), hi/lo
        float rs0 = 0.f, rs1 = 0.f;
        #pragma unroll
        for (int n = 0; n < 8; n++) {
            const float p0 = __expf(s[n][0] - m0);
            const float p1 = __expf(s[n][1] - m0);
            const float p2 = __expf(s[n][2] - m1);
            const float p3 = __expf(s[n][3] - m1);
            rs0 += p0 + p1; rs1 += p2 + p3;
            const bf16 h0 = __float2bfloat16(p0), h1 = __float2bfloat16(p1);
            const bf16 h2 = __float2bfloat16(p2), h3 = __float2bfloat16(p3);
            __nv_bfloat162 t;
            t = __halves2bfloat162(h0, h1); pA[n]  = *(uint32_t*)&t;
            t = __halves2bfloat162(h2, h3); pB[n]  = *(uint32_t*)&t;
            t = __floats2bfloat162_rn(p0 - __bfloat162float(h0), p1 - __bfloat162float(h1));
            pAl[n] = *(uint32_t*)&t;
            t = __floats2bfloat162_rn(p2 - __bfloat162float(h2), p3 - __bfloat162float(h3));
            pBl[n] = *(uint32_t*)&t;
        }
        rs0 += __shfl_xor_sync(0xffffffffu, rs0, 1);
        rs0 += __shfl_xor_sync(0xffffffffu, rs0, 2);
        rs1 += __shfl_xor_sync(0xffffffffu, rs1, 1);
        rs1 += __shfl_xor_sync(0xffffffffu, rs1, 2);
        l0 = l0 * a0 + rs0;
        l1 = l1 * a1 + rs1;
        #pragma unroll
        for (int n = 0; n < 8; n++) {
            o[n][0] *= a0; o[n][1] *= a0;
            o[n][2] *= a1; o[n][3] *= a1;
        }

        // ---- O += P V ----
        #pragma unroll
        for (int j = 0; j < 4; j++) {          // kv k16 steps
            uint32_t aH[4] = {pA[2*j], pB[2*j], pA[2*j+1], pB[2*j+1]};
            uint32_t aL[4] = {pAl[2*j], pBl[2*j], pAl[2*j+1], pBl[2*j+1]};
            #pragma unroll
            for (int p2 = 0; p2 < 4; p2++) {   // head-dim n-tile pairs
                const uint32_t off = (uint32_t)((p2 * 16 + b_row) * AQP + j * 16 + b_kof) * 2;
                uint32_t rh[4], rl[4];
                ldsm4(rh, scvta(VH) + off);
                ldsm4(rl, scvta(VL) + off);
                mma16816(o[2 * p2],     aH, rh[0], rh[1]);
                mma16816(o[2 * p2],     aH, rl[0], rl[1]);
                mma16816(o[2 * p2],     aL, rh[0], rh[1]);
                mma16816(o[2 * p2 + 1], aH, rh[2], rh[3]);
                mma16816(o[2 * p2 + 1], aH, rl[2], rl[3]);
                mma16816(o[2 * p2 + 1], aL, rh[2], rh[3]);
            }
        }
        __syncthreads();
    }

    // ---- epilogue: normalize, split to bf16 hi/lo, store ----
    const float i0 = 1.f / l0, i1 = 1.f / l1;
    #pragma unroll
    for (int n = 0; n < 8; n++) {
        const int col = h * HD + n * 8 + lc;
        {
            const float v0 = o[n][0] * i0, v1 = o[n][1] * i0;
            const bf16 b0 = __float2bfloat16(v0), b1 = __float2bfloat16(v1);
            __nv_bfloat162 t = __halves2bfloat162(b0, b1);
            *(uint32_t*)(oh + (size_t)row0g * DMODEL + col) = *(uint32_t*)&t;
            t = __floats2bfloat162_rn(v0 - __bfloat162float(b0), v1 - __bfloat162float(b1));
            *(uint32_t*)(ol + (size_t)row0g * DMODEL + col) = *(uint32_t*)&t;
        }
        {
            const float v0 = o[n][2] * i1, v1 = o[n][3] * i1;
            const bf16 b0 = __float2bfloat16(v0), b1 = __float2bfloat16(v1);
            __nv_bfloat162 t = __halves2bfloat162(b0, b1);
            *(uint32_t*)(oh + (size_t)row1g * DMODEL + col) = *(uint32_t*)&t;
            t = __floats2bfloat162_rn(v0 - __bfloat162float(b0), v1 - __bfloat162float(b1));
            *(uint32_t*)(ol + (size_t)row1g * DMODEL + col) = *(uint32_t*)&t;
        }
    }
}

// ----------------------------------------------------------------------------
// Launch
// ----------------------------------------------------------------------------
extern "C" void kernel_launch(void* const* d_in, const int* in_sizes, int n_in,
                              void* d_out, int out_size) {
    const float* x  = (const float*)d_in[0];
    const float* g  = (const float*)d_in[1];
    const float* wq = (const float*)d_in[2];
    const float* wk = (const float*)d_in[3];
    const float* wv = (const float*)d_in[4];
    const float* wo = (const float*)d_in[5];
    float* out = (float*)d_out;

    static bool inited = false;
    static bf16 *hh, *hl, *wqh, *wql, *kvth, *kvtl, *woh, *wol;
    static bf16 *qh, *ql, *kh, *kl, *vh, *vl, *oh, *ol;
    static float *pq, *pkv;
    if (!inited) {
        inited = true;
        cudaFuncSetAttribute(mma_gemm_kernel,
                             cudaFuncAttributeMaxDynamicSharedMemorySize, GEMM_SMEM);
        cudaGetSymbolAddress((void**)&hh,   g_hh);
        cudaGetSymbolAddress((void**)&hl,   g_hl);
        cudaGetSymbolAddress((void**)&wqh,  g_wqh);
        cudaGetSymbolAddress((void**)&wql,  g_wql);
        cudaGetSymbolAddress((void**)&kvth, g_kvh);
        cudaGetSymbolAddress((void**)&kvtl, g_kvl);
        cudaGetSymbolAddress((void**)&woh,  g_woh);
        cudaGetSymbolAddress((void**)&wol,  g_wol);
        cudaGetSymbolAddress((void**)&qh,   g_qh);
        cudaGetSymbolAddress((void**)&ql,   g_ql);
        cudaGetSymbolAddress((void**)&kh,   g_kh);
        cudaGetSymbolAddress((void**)&kl,   g_kl);
        cudaGetSymbolAddress((void**)&vh,   g_vh);
        cudaGetSymbolAddress((void**)&vl,   g_vl);
        cudaGetSymbolAddress((void**)&oh,   g_oh);
        cudaGetSymbolAddress((void**)&ol,   g_ol);
        cudaGetSymbolAddress((void**)&pq,   g_pq);
        cudaGetSymbolAddress((void**)&pkv,  g_pkv);
    }

    // 1) RMSNorm -> bf16 split
    rmsnorm_kernel<<<S_LEN, 256>>>(x, g, hh, hl);

    // 2) Weight transpose + split (wk, wv fused into one [1024][2048] operand)
    dim3 tb(32, 8);
    transpose_split_kernel<<<dim3(DMODEL / 32, DMODEL / 32), tb>>>(wq, wqh, wql, DMODEL, DMODEL);
    transpose_split_kernel<<<dim3(KV_DIM / 32, DMODEL / 32), tb>>>(wk, kvth, kvtl, DMODEL, KV_DIM);
    transpose_split_kernel<<<dim3(KV_DIM / 32, DMODEL / 32), tb>>>(
        wv, kvth + (size_t)KV_DIM * DMODEL, kvtl + (size_t)KV_DIM * DMODEL, DMODEL, KV_DIM);
    transpose_split_kernel<<<dim3(DMODEL / 32, DMODEL / 32), tb>>>(wo, woh, wol, DMODEL, DMODEL);

    // 3) Projections (bf16x3 on HMMA, cp.async pipelined)
    mma_gemm_kernel<<<dim3(DMODEL / 128, S_LEN / 128), 256, GEMM_SMEM>>>(
        hh, hl, wqh, wql, nullptr, pq, DMODEL, DMODEL);
    mma_gemm_kernel<<<dim3(2 * KV_DIM / 128, S_LEN / 128), 256, GEMM_SMEM>>>(
        hh, hl, kvth, kvtl, nullptr, pkv, 2 * KV_DIM, DMODEL);

    // 4) RoPE + split (q scaled by 1/sqrt(HD)); V split
    {
        const int tq = S_LEN * HQ * 32;
        rope_split_kernel<<<(tq + 255) / 256, 256>>>(pq, DMODEL, qh, ql, DMODEL, HQ, 0.125f, tq);
        const int tk = S_LEN * HKV * 32;
        rope_split_kernel<<<(tk + 255) / 256, 256>>>(pkv, 2 * KV_DIM, kh, kl, KV_DIM, HKV, 1.0f, tk);
        split_v_kernel<<<(S_LEN * KV_DIM + 255) / 256, 256>>>(pkv, vh, vl);
    }

    // 5) Tensor-core flash attention (writes bf16 split O)
    attn_mma_kernel<<<dim3(HQ, S_LEN / 128), 256>>>(qh, ql, kh, kl, vh, vl, oh, ol);

    // 6) Output projection + residual
    mma_gemm_kernel<<<dim3(DMODEL / 128, S_LEN / 128), 256, GEMM_SMEM>>>(
        oh, ol, woh, wol, x, out, DMODEL, DMODEL);
}

// round 5
// speedup vs baseline: 2.7007x; 1.0510x over previous
#include <cuda_runtime.h>
#include <cuda_bf16.h>
#include <cstdint>
#include <math.h>

// ----------------------------------------------------------------------------
// Problem constants
// ----------------------------------------------------------------------------
#define S_LEN   2048
#define DMODEL  2048
#define HQ      32
#define HKV     8
#define HD      64
#define KV_DIM  (HKV*HD)   // 512

typedef __nv_bfloat16 bf16;

// ----------------------------------------------------------------------------
// Scratch (static __device__ arrays: allocation-free)
// ----------------------------------------------------------------------------
__device__ bf16  g_hh[S_LEN * DMODEL],  g_hl[S_LEN * DMODEL];
__device__ bf16  g_wqh[DMODEL * DMODEL], g_wql[DMODEL * DMODEL];
__device__ bf16  g_kvh[2 * KV_DIM * DMODEL], g_kvl[2 * KV_DIM * DMODEL];
__device__ bf16  g_woh[DMODEL * DMODEL], g_wol[DMODEL * DMODEL];
__device__ float g_pq[S_LEN * DMODEL];
__device__ float g_pkv[S_LEN * 2 * KV_DIM];
__device__ bf16  g_qh[S_LEN * DMODEL],  g_ql[S_LEN * DMODEL];
__device__ bf16  g_kh[S_LEN * KV_DIM],  g_kl[S_LEN * KV_DIM];
__device__ bf16  g_vh[S_LEN * KV_DIM],  g_vl[S_LEN * KV_DIM];
__device__ bf16  g_oh[S_LEN * DMODEL],  g_ol[S_LEN * DMODEL];

// ----------------------------------------------------------------------------
// PTX helpers (sm_80+ features only — legal on plain compute_103)
// ----------------------------------------------------------------------------
__device__ __forceinline__ void mma16816(float* c, const uint32_t* a,
                                         uint32_t b0, uint32_t b1) {
    asm volatile(
        "mma.sync.aligned.m16n8k16.row.col.f32.bf16.bf16.f32 "
        "{%0,%1,%2,%3}, {%4,%5,%6,%7}, {%8,%9}, {%0,%1,%2,%3};"
        : "+f"(c[0]), "+f"(c[1]), "+f"(c[2]), "+f"(c[3])
        : "r"(a[0]), "r"(a[1]), "r"(a[2]), "r"(a[3]), "r"(b0), "r"(b1));
}
__device__ __forceinline__ void ldsm4(uint32_t* r, uint32_t addr) {
    asm volatile("ldmatrix.sync.aligned.m8n8.x4.shared.b16 {%0,%1,%2,%3}, [%4];"
                 : "=r"(r[0]), "=r"(r[1]), "=r"(r[2]), "=r"(r[3]) : "r"(addr));
}
__device__ __forceinline__ void ldsm4t(uint32_t* r, uint32_t addr) {
    asm volatile("ldmatrix.sync.aligned.m8n8.x4.trans.shared.b16 {%0,%1,%2,%3}, [%4];"
                 : "=r"(r[0]), "=r"(r[1]), "=r"(r[2]), "=r"(r[3]) : "r"(addr));
}
__device__ __forceinline__ void cp16(uint32_t saddr, const void* g) {
    asm volatile("cp.async.cg.shared.global [%0], [%1], 16;" :: "r"(saddr), "l"(g));
}
__device__ __forceinline__ void cp_commit() {
    asm volatile("cp.async.commit_group;" ::: "memory");
}
__device__ __forceinline__ uint32_t scvta(const void* p) {
    return (uint32_t)__cvta_generic_to_shared(p);
}
__device__ __forceinline__ uint32_t pack_bf16(float a, float b) {
    __nv_bfloat162 t = __floats2bfloat162_rn(a, b);
    return *(uint32_t*)&t;
}

// ----------------------------------------------------------------------------
// RMSNorm (vectorized): one block per row; writes bf16 hi/lo split
// ----------------------------------------------------------------------------
__global__ void rmsnorm_kernel(const float* __restrict__ x,
                               const float* __restrict__ g,
                               bf16* __restrict__ hh, bf16* __restrict__ hl) {
    const int s = blockIdx.x;
    const float2* xr = (const float2*)(x + (size_t)s * DMODEL);
    const float2* gr = (const float2*)g;
    float sum = 0.f;
    #pragma unroll
    for (int d = threadIdx.x; d < DMODEL / 2; d += 256) {
        float2 v = xr[d];
        sum += v.x * v.x + v.y * v.y;
    }
    __shared__ float red[8];
    #pragma unroll
    for (int o = 16; o > 0; o >>= 1) sum += __shfl_xor_sync(0xffffffffu, sum, o);
    if ((threadIdx.x & 31) == 0) red[threadIdx.x >> 5] = sum;
    __syncthreads();
    if (threadIdx.x < 32) {
        float v = (threadIdx.x < 8) ? red[threadIdx.x] : 0.f;
        #pragma unroll
        for (int o = 4; o > 0; o >>= 1) v += __shfl_xor_sync(0xffffffffu, v, o);
        if (threadIdx.x == 0) red[0] = v;
    }
    __syncthreads();
    const float rinv = rsqrtf(red[0] / (float)DMODEL + 1e-9f);
    uint32_t* ph = (uint32_t*)(hh + (size_t)s * DMODEL);
    uint32_t* pl = (uint32_t*)(hl + (size_t)s * DMODEL);
    #pragma unroll
    for (int d = threadIdx.x; d < DMODEL / 2; d += 256) {
        const float2 v = xr[d];
        const float2 gg = gr[d];
        const float a = v.x * rinv * gg.x, b = v.y * rinv * gg.y;
        const bf16 ha = __float2bfloat16(a), hb = __float2bfloat16(b);
        __nv_bfloat162 t = __halves2bfloat162(ha, hb);
        ph[d] = *(uint32_t*)&t;
        pl[d] = pack_bf16(a - __bfloat162float(ha), b - __bfloat162float(hb));
    }
}

// ----------------------------------------------------------------------------
// Transpose + bf16 split (vectorized stores): W[K,N] fp32 -> Wt hi/lo [N,K]
// ----------------------------------------------------------------------------
__global__ void transpose_split_kernel(const float* __restrict__ w,
                                       bf16* __restrict__ th, bf16* __restrict__ tl,
                                       int K, int N) {
    __shared__ float t[32][33];
    const int n0 = blockIdx.x * 32, k0 = blockIdx.y * 32;
    const int tx = threadIdx.x, ty = threadIdx.y;  // (32, 8)
    #pragma unroll
    for (int i = 0; i < 32; i += 8)
        t[ty + i][tx] = w[(size_t)(k0 + ty + i) * N + n0 + tx];
    __syncthreads();
    const int lt = ty * 32 + tx;        // 0..255
    const int n  = lt >> 3;             // 0..31
    const int kp = lt & 7;              // 0..7
    #pragma unroll
    for (int q = 0; q < 2; q++) {
        const int k2 = (kp + q * 8) * 2;
        const float v0 = t[k2][n], v1 = t[k2 + 1][n];
        const bf16 h0 = __float2bfloat16(v0), h1 = __float2bfloat16(v1);
        __nv_bfloat162 hp = __halves2bfloat162(h0, h1);
        const size_t o = (size_t)(n0 + n) * K + k0 + k2;
        *(uint32_t*)(th + o) = *(uint32_t*)&hp;
        *(uint32_t*)(tl + o) = pack_bf16(v0 - __bfloat162float(h0),
                                         v1 - __bfloat162float(h1));
    }
}

// ----------------------------------------------------------------------------
// bf16x3 GEMM v3: 3-stage cp.async + ldmatrix, warp tile 64x(BN/4).
// C[M,N] = A @ B^T (+Res). Block 128xBN, BK=32, 256 thr = 8 warps (2M x 4N).
// ----------------------------------------------------------------------------
#define KP 40
#define NSTAGE 3
#define A_STG (128 * KP * 2)

template<int BN>
__global__ __launch_bounds__(256, 1) void mma_gemm_kernel(
    const bf16* __restrict__ Ah, const bf16* __restrict__ Al,
    const bf16* __restrict__ Bh, const bf16* __restrict__ Bl,
    const float* __restrict__ Res, float* __restrict__ C,
    int N, int K) {
    constexpr int B_STG = BN * KP * 2;
    constexpr int NT = BN / 32;          // n-tiles (8-wide) per warp
    extern __shared__ __align__(16) char sm[];
    const uint32_t smb = scvta(sm);
    const uint32_t oAH = 0;
    const uint32_t oAL = NSTAGE * A_STG;
    const uint32_t oBH = 2 * NSTAGE * A_STG;
    const uint32_t oBL = 2 * NSTAGE * A_STG + NSTAGE * B_STG;

    const int tid  = threadIdx.x;
    const int lane = tid & 31, wid = tid >> 5;
    const int bm = blockIdx.y * 128, bn = blockIdx.x * BN;
    const int wmb = (wid & 1) * 64;
    const int wnb = (wid >> 1) * (BN / 4);
    const int lr = lane >> 2, lc = (lane & 3) * 2;

    float acc[4][NT][4];
    #pragma unroll
    for (int mt = 0; mt < 4; mt++)
        #pragma unroll
        for (int nt = 0; nt < NT; nt++)
            #pragma unroll
            for (int i = 0; i < 4; i++) acc[mt][nt][i] = 0.f;

    auto load_stage = [&](int s, int kc) {
        #pragma unroll
        for (int p = 0; p < 2; p++) {               // A: 512 chunks
            const int idx = tid + p * 256;
            const int r = idx >> 2, c8 = (idx & 3) * 8;
            const uint32_t off = (uint32_t)(r * KP + c8) * 2;
            const size_t ga = (size_t)(bm + r) * K + kc + c8;
            cp16(smb + oAH + s * A_STG + off, Ah + ga);
            cp16(smb + oAL + s * A_STG + off, Al + ga);
        }
        #pragma unroll
        for (int p = 0; p < BN / 64; p++) {         // B: BN*4 chunks
            const int idx = tid + p * 256;
            const int r = idx >> 2, c8 = (idx & 3) * 8;
            const uint32_t off = (uint32_t)(r * KP + c8) * 2;
            const size_t gb = (size_t)(bn + r) * K + kc + c8;
            cp16(smb + oBH + s * B_STG + off, Bh + gb);
            cp16(smb + oBL + s * B_STG + off, Bl + gb);
        }
    };

    const int nch = K >> 5;
    load_stage(0, 0);
    cp_commit();
    load_stage(1, 32);
    cp_commit();

    const int a_row = lane & 15;
    const int a_kof = (lane >> 4) << 3;
    const int b_row = (lane & 7) + ((lane >> 4) << 3);
    const int b_kof = ((lane >> 3) & 1) << 3;

    for (int c = 0; c < nch; c++) {
        if (c + 1 < nch) asm volatile("cp.async.wait_group 1;" ::: "memory");
        else             asm volatile("cp.async.wait_group 0;" ::: "memory");
        __syncthreads();
        if (c + 2 < nch) {
            load_stage((c + 2) % NSTAGE, (c + 2) * 32);
            cp_commit();
        }
        const int cur = c % NSTAGE;
        const uint32_t sAh = smb + oAH + cur * A_STG;
        const uint32_t sAl = smb + oAL + cur * A_STG;
        const uint32_t sBh = smb + oBH + cur * B_STG;
        const uint32_t sBl = smb + oBL + cur * B_STG;

        #pragma unroll
        for (int kk = 0; kk < 32; kk += 16) {
            uint32_t fah[4][4], fal[4][4];
            #pragma unroll
            for (int mt = 0; mt < 4; mt++) {
                const uint32_t off = (uint32_t)((wmb + mt * 16 + a_row) * KP + kk + a_kof) * 2;
                ldsm4(fah[mt], sAh + off);
                ldsm4(fal[mt], sAl + off);
            }
            #pragma unroll
            for (int p2 = 0; p2 < NT / 2; p2++) {
                const uint32_t off = (uint32_t)((wnb + p2 * 16 + b_row) * KP + kk + b_kof) * 2;
                uint32_t rh[4], rl[4];
                ldsm4(rh, sBh + off);
                ldsm4(rl, sBl + off);
                #pragma unroll
                for (int mt = 0; mt < 4; mt++) {
                    mma16816(acc[mt][2 * p2],     fah[mt], rh[0], rh[1]);
                    mma16816(acc[mt][2 * p2],     fah[mt], rl[0], rl[1]);
                    mma16816(acc[mt][2 * p2],     fal[mt], rh[0], rh[1]);
                    mma16816(acc[mt][2 * p2 + 1], fah[mt], rh[2], rh[3]);
                    mma16816(acc[mt][2 * p2 + 1], fah[mt], rl[2], rl[3]);
                    mma16816(acc[mt][2 * p2 + 1], fal[mt], rh[2], rh[3]);
                }
            }
        }
        __syncthreads();
    }

    #pragma unroll
    for (int mt = 0; mt < 4; mt++) {
        const int row0 = bm + wmb + mt * 16 + lr;
        #pragma unroll
        for (int nt = 0; nt < NT; nt++) {
            const int col = bn + wnb + nt * 8 + lc;
            float2 v0 = make_float2(acc[mt][nt][0], acc[mt][nt][1]);
            float2 v1 = make_float2(acc[mt][nt][2], acc[mt][nt][3]);
            if (Res) {
                const float2 q0 = *(const float2*)(Res + (size_t)row0 * N + col);
                const float2 q1 = *(const float2*)(Res + (size_t)(row0 + 8) * N + col);
                v0.x += q0.x; v0.y += q0.y;
                v1.x += q1.x; v1.y += q1.y;
            }
            *(float2*)(C + (size_t)row0 * N + col) = v0;
            *(float2*)(C + (size_t)(row0 + 8) * N + col) = v1;
        }
    }
}

// ----------------------------------------------------------------------------
// RoPE + scale + bf16 split (vectorized). Thread handles dims (2i,2i+1,+32,+33).
// ----------------------------------------------------------------------------
__global__ void rope_split_kernel(const float* __restrict__ src, int src_stride,
                                  bf16* __restrict__ oh, bf16* __restrict__ ol,
                                  int o_stride, int H, float scale, int total) {
    int idx = blockIdx.x * blockDim.x + threadIdx.x;
    if (idx >= total) return;
    const int i2 = idx & 15;
    const int h = (idx >> 4) % H;
    const int s = idx / (16 * H);
    const float* p = src + (size_t)s * src_stride + h * HD;
    float y[4];
    #pragma unroll
    for (int q = 0; q < 2; q++) {
        const int i = 2 * i2 + q;
        const double inv = pow(10000.0, -(double)(2 * i) / (double)HD);
        const double ang = (double)s * inv;
        const float cs = (float)cos(ang);
        const float sn = (float)sin(ang);
        const float x1 = p[i], x2 = p[i + 32];
        y[q]     = (x1 * cs - x2 * sn) * scale;
        y[2 + q] = (x1 * sn + x2 * cs) * scale;
    }
    bf16* ph = oh + (size_t)s * o_stride + h * HD;
    bf16* pl = ol + (size_t)s * o_stride + h * HD;
    const bf16 b0 = __float2bfloat16(y[0]), b1 = __float2bfloat16(y[1]);
    const bf16 b2 = __float2bfloat16(y[2]), b3 = __float2bfloat16(y[3]);
    __nv_bfloat162 t;
    t = __halves2bfloat162(b0, b1); *(uint32_t*)(ph + 2 * i2) = *(uint32_t*)&t;
    t = __halves2bfloat162(b2, b3); *(uint32_t*)(ph + 2 * i2 + 32) = *(uint32_t*)&t;
    *(uint32_t*)(pl + 2 * i2)      = pack_bf16(y[0] - __bfloat162float(b0),
                                               y[1] - __bfloat162float(b1));
    *(uint32_t*)(pl + 2 * i2 + 32) = pack_bf16(y[2] - __bfloat162float(b2),
                                               y[3] - __bfloat162float(b3));
}

// ----------------------------------------------------------------------------
// Strided bf16 split for V (vectorized)
// ----------------------------------------------------------------------------
__global__ void split_v_kernel(const float* __restrict__ src,
                               bf16* __restrict__ hi, bf16* __restrict__ lo) {
    int i = blockIdx.x * blockDim.x + threadIdx.x;
    if (i >= S_LEN * KV_DIM / 2) return;
    const int s = i >> 8, c2 = (i & 255) * 2;
    const float2 v = *(const float2*)(src + (size_t)s * (2 * KV_DIM) + KV_DIM + c2);
    const bf16 h0 = __float2bfloat16(v.x), h1 = __float2bfloat16(v.y);
    __nv_bfloat162 t = __halves2bfloat162(h0, h1);
    *(uint32_t*)(hi + (size_t)s * KV_DIM + c2) = *(uint32_t*)&t;
    *(uint32_t*)(lo + (size_t)s * KV_DIM + c2) =
        pack_bf16(v.x - __bfloat162float(h0), v.y - __bfloat162float(h1));
}

// ----------------------------------------------------------------------------
// Tensor-core causal GQA flash attention (bf16x3).
// Grid (S/128, HQ) for wave balance. 256 threads = 8 warps x 16 q-rows.
// V stays row-major; PV fragments via ldmatrix.trans.
// ----------------------------------------------------------------------------
#define AQP 72

__global__ __launch_bounds__(256) void attn_mma_kernel(
    const bf16* __restrict__ qh, const bf16* __restrict__ ql,
    const bf16* __restrict__ kh, const bf16* __restrict__ kl,
    const bf16* __restrict__ vh, const bf16* __restrict__ vl,
    bf16* __restrict__ oh, bf16* __restrict__ ol) {
    __shared__ __align__(16) char sbuf[36864];
    bf16* QH = (bf16*)sbuf;                 // [128][72]
    bf16* QL = (bf16*)(sbuf + 18432);
    bf16* KH = (bf16*)sbuf;                 // [64][72]
    bf16* KL = (bf16*)(sbuf + 9216);
    bf16* VH = (bf16*)(sbuf + 18432);       // [64 kv][72]  (natural layout)
    bf16* VL = (bf16*)(sbuf + 27648);

    const int qt = blockIdx.x, h = blockIdx.y;
    const int kvh = h >> 2;
    const int tid = threadIdx.x, lane = tid & 31, wid = tid >> 5;
    const int lr = lane >> 2, lc = (lane & 3) * 2;

    // ---- stage Q ----
    #pragma unroll
    for (int p = 0; p < 4; p++) {
        const int idx = tid + p * 256;
        const int r = idx >> 3, c8 = (idx & 7) * 8;
        const size_t go = (size_t)(qt * 128 + r) * DMODEL + h * HD + c8;
        *(uint4*)(QH + r * AQP + c8) = *(const uint4*)(qh + go);
        *(uint4*)(QL + r * AQP + c8) = *(const uint4*)(ql + go);
    }
    __syncthreads();

    uint32_t qfh[4][4], qfl[4][4];
    {
        const int a_row = lane & 15;
        const int a_kof = (lane >> 4) << 3;
        #pragma unroll
        for (int ks = 0; ks < 4; ks++) {
            const uint32_t off = (uint32_t)((wid * 16 + a_row) * AQP + ks * 16 + a_kof) * 2;
            ldsm4(qfh[ks], scvta(QH) + off);
            ldsm4(qfl[ks], scvta(QL) + off);
        }
    }
    __syncthreads();

    float o[8][4];
    #pragma unroll
    for (int n = 0; n < 8; n++)
        #pragma unroll
        for (int i = 0; i < 4; i++) o[n][i] = 0.f;
    float m0 = -1e30f, m1 = -1e30f, l0 = 0.f, l1 = 0.f;

    const int row0g = qt * 128 + wid * 16 + lr;
    const int row1g = row0g + 8;
    const int nkt = 2 * qt + 2;

    const int b_row = (lane & 7) + ((lane >> 4) << 3);
    const int b_kof = ((lane >> 3) & 1) << 3;
    const int v_row = lane & 15;
    const int v_col = (lane >> 4) << 3;

    for (int kt = 0; kt < nkt; kt++) {
        // ---- load K and V tiles (both natural [kv][d], uint4) ----
        #pragma unroll
        for (int p = 0; p < 2; p++) {
            const int idx = tid + p * 256;
            const int r = idx >> 3, c8 = (idx & 7) * 8;
            const size_t go = (size_t)(kt * 64 + r) * KV_DIM + kvh * HD + c8;
            *(uint4*)(KH + r * AQP + c8) = *(const uint4*)(kh + go);
            *(uint4*)(KL + r * AQP + c8) = *(const uint4*)(kl + go);
            *(uint4*)(VH + r * AQP + c8) = *(const uint4*)(vh + go);
            *(uint4*)(VL + r * AQP + c8) = *(const uint4*)(vl + go);
        }
        __syncthreads();

        // ---- S = Q K^T ----
        float s[8][4];
        #pragma unroll
        for (int n = 0; n < 8; n++)
            #pragma unroll
            for (int i = 0; i < 4; i++) s[n][i] = 0.f;
        #pragma unroll
        for (int ks = 0; ks < 4; ks++) {
            #pragma unroll
            for (int p2 = 0; p2 < 4; p2++) {
                const uint32_t off = (uint32_t)((p2 * 16 + b_row) * AQP + ks * 16 + b_kof) * 2;
                uint32_t rh[4], rl[4];
                ldsm4(rh, scvta(KH) + off);
                ldsm4(rl, scvta(KL) + off);
                mma16816(s[2 * p2],     qfh[ks], rh[0], rh[1]);
                mma16816(s[2 * p2],     qfh[ks], rl[0], rl[1]);
                mma16816(s[2 * p2],     qfl[ks], rh[0], rh[1]);
                mma16816(s[2 * p2 + 1], qfh[ks], rh[2], rh[3]);
                mma16816(s[2 * p2 + 1], qfh[ks], rl[2], rl[3]);
                mma16816(s[2 * p2 + 1], qfl[ks], rh[2], rh[3]);
            }
        }

        // ---- causal mask ----
        if (kt >= 2 * qt) {
            #pragma unroll
            for (int n = 0; n < 8; n++) {
                const int colb = kt * 64 + n * 8 + lc;
                if (colb     > row0g) s[n][0] = -1e30f;
                if (colb + 1 > row0g) s[n][1] = -1e30f;
                if (colb     > row1g) s[n][2] = -1e30f;
                if (colb + 1 > row1g) s[n][3] = -1e30f;
            }
        }

        // ---- online softmax ----
        float tm0 = -1e30f, tm1 = -1e30f;
        #pragma unroll
        for (int n = 0; n < 8; n++) {
            tm0 = fmaxf(tm0, fmaxf(s[n][0], s[n][1]));
            tm1 = fmaxf(tm1, fmaxf(s[n][2], s[n][3]));
        }
        tm0 = fmaxf(tm0, __shfl_xor_sync(0xffffffffu, tm0, 1));
        tm0 = fmaxf(tm0, __shfl_xor_sync(0xffffffffu, tm0, 2));
        tm1 = fmaxf(tm1, __shfl_xor_sync(0xffffffffu, tm1, 1));
        tm1 = fmaxf(tm1, __shfl_xor_sync(0xffffffffu, tm1, 2));
        const float mn0 = fmaxf(m0, tm0), mn1 = fmaxf(m1, tm1);
        const float a0 = __expf(m0 - mn0), a1 = __expf(m1 - mn1);
        m0 = mn0; m1 = mn1;

        uint32_t pA[8], pB[8], pAl[8], pBl[8];
        float rs0 = 0.f, rs1 = 0.f;
        #pragma unroll
        for (int n = 0; n < 8; n++) {
            const float p0 = __expf(s[n][0] - m0);
            const float p1 = __expf(s[n][1] - m0);
            const float p2 = __expf(s[n][2] - m1);
            const float p3 = __expf(s[n][3] - m1);
            rs0 += p0 + p1; rs1 += p2 + p3;
            const bf16 h0 = __float2bfloat16(p0), h1 = __float2bfloat16(p1);
            const bf16 h2 = __float2bfloat16(p2), h3 = __float2bfloat16(p3);
            __nv_bfloat162 t;
            t = __halves2bfloat162(h0, h1); pA[n] = *(uint32_t*)&t;
            t = __halves2bfloat162(h2, h3); pB[n] = *(uint32_t*)&t;
            pAl[n] = pack_bf16(p0 - __bfloat162float(h0), p1 - __bfloat162float(h1));
            pBl[n] = pack_bf16(p2 - __bfloat162float(h2), p3 - __bfloat162float(h3));
        }
        rs0 += __shfl_xor_sync(0xffffffffu, rs0, 1);
        rs0 += __shfl_xor_sync(0xffffffffu, rs0, 2);
        rs1 += __shfl_xor_sync(0xffffffffu, rs1, 1);
        rs1 += __shfl_xor_sync(0xffffffffu, rs1, 2);
        l0 = l0 * a0 + rs0;
        l1 = l1 * a1 + rs1;
        #pragma unroll
        for (int n = 0; n < 8; n++) {
            o[n][0] *= a0; o[n][1] *= a0;
            o[n][2] *= a1; o[n][3] *= a1;
        }

        // ---- O += P V  (V fragments via ldmatrix.trans on natural layout) ----
        #pragma unroll
        for (int j = 0; j < 4; j++) {
            uint32_t aH[4] = {pA[2*j], pB[2*j], pA[2*j+1], pB[2*j+1]};
            uint32_t aL[4] = {pAl[2*j], pBl[2*j], pAl[2*j+1], pBl[2*j+1]};
            #pragma unroll
            for (int p2 = 0; p2 < 4; p2++) {
                const uint32_t off =
                    (uint32_t)((j * 16 + v_row) * AQP + p2 * 16 + v_col) * 2;
                uint32_t rh[4], rl[4];
                ldsm4t(rh, scvta(VH) + off);
                ldsm4t(rl, scvta(VL) + off);
                mma16816(o[2 * p2],     aH, rh[0], rh[1]);
                mma16816(o[2 * p2],     aH, rl[0], rl[1]);
                mma16816(o[2 * p2],     aL, rh[0], rh[1]);
                mma16816(o[2 * p2 + 1], aH, rh[2], rh[3]);
                mma16816(o[2 * p2 + 1], aH, rl[2], rl[3]);
                mma16816(o[2 * p2 + 1], aL, rh[2], rh[3]);
            }
        }
        __syncthreads();
    }

    // ---- epilogue ----
    const float i0 = 1.f / l0, i1 = 1.f / l1;
    #pragma unroll
    for (int n = 0; n < 8; n++) {
        const int col = h * HD + n * 8 + lc;
        {
            const float v0 = o[n][0] * i0, v1 = o[n][1] * i0;
            const bf16 b0 = __float2bfloat16(v0), b1 = __float2bfloat16(v1);
            __nv_bfloat162 t = __halves2bfloat162(b0, b1);
            *(uint32_t*)(oh + (size_t)row0g * DMODEL + col) = *(uint32_t*)&t;
            *(uint32_t*)(ol + (size_t)row0g * DMODEL + col) =
                pack_bf16(v0 - __bfloat162float(b0), v1 - __bfloat162float(b1));
        }
        {
            const float v0 = o[n][2] * i1, v1 = o[n][3] * i1;
            const bf16 b0 = __float2bfloat16(v0), b1 = __float2bfloat16(v1);
            __nv_bfloat162 t = __halves2bfloat162(b0, b1);
            *(uint32_t*)(oh + (size_t)row1g * DMODEL + col) = *(uint32_t*)&t;
            *(uint32_t*)(ol + (size_t)row1g * DMODEL + col) =
                pack_bf16(v0 - __bfloat162float(b0), v1 - __bfloat162float(b1));
        }
    }
}

// ----------------------------------------------------------------------------
// Launch
// ----------------------------------------------------------------------------
#define GEMM_SMEM_256 (2 * NSTAGE * A_STG + 2 * NSTAGE * (256 * KP * 2))
#define GEMM_SMEM_128 (2 * NSTAGE * A_STG + 2 * NSTAGE * (128 * KP * 2))

extern "C" void kernel_launch(void* const* d_in, const int* in_sizes, int n_in,
                              void* d_out, int out_size) {
    const float* x  = (const float*)d_in[0];
    const float* g  = (const float*)d_in[1];
    const float* wq = (const float*)d_in[2];
    const float* wk = (const float*)d_in[3];
    const float* wv = (const float*)d_in[4];
    const float* wo = (const float*)d_in[5];
    float* out = (float*)d_out;

    static bool inited = false;
    static bf16 *hh, *hl, *wqh, *wql, *kvth, *kvtl, *woh, *wol;
    static bf16 *qh, *ql, *kh, *kl, *vh, *vl, *oh, *ol;
    static float *pq, *pkv;
    if (!inited) {
        inited = true;
        cudaFuncSetAttribute(mma_gemm_kernel<256>,
                             cudaFuncAttributeMaxDynamicSharedMemorySize, GEMM_SMEM_256);
        cudaFuncSetAttribute(mma_gemm_kernel<128>,
                             cudaFuncAttributeMaxDynamicSharedMemorySize, GEMM_SMEM_128);
        cudaGetSymbolAddress((void**)&hh,   g_hh);
        cudaGetSymbolAddress((void**)&hl,   g_hl);
        cudaGetSymbolAddress((void**)&wqh,  g_wqh);
        cudaGetSymbolAddress((void**)&wql,  g_wql);
        cudaGetSymbolAddress((void**)&kvth, g_kvh);
        cudaGetSymbolAddress((void**)&kvtl, g_kvl);
        cudaGetSymbolAddress((void**)&woh,  g_woh);
        cudaGetSymbolAddress((void**)&wol,  g_wol);
        cudaGetSymbolAddress((void**)&qh,   g_qh);
        cudaGetSymbolAddress((void**)&ql,   g_ql);
        cudaGetSymbolAddress((void**)&kh,   g_kh);
        cudaGetSymbolAddress((void**)&kl,   g_kl);
        cudaGetSymbolAddress((void**)&vh,   g_vh);
        cudaGetSymbolAddress((void**)&vl,   g_vl);
        cudaGetSymbolAddress((void**)&oh,   g_oh);
        cudaGetSymbolAddress((void**)&ol,   g_ol);
        cudaGetSymbolAddress((void**)&pq,   g_pq);
        cudaGetSymbolAddress((void**)&pkv,  g_pkv);
    }

    // 1) RMSNorm -> bf16 split
    rmsnorm_kernel<<<S_LEN, 256>>>(x, g, hh, hl);

    // 2) Weight transpose + split
    dim3 tb(32, 8);
    transpose_split_kernel<<<dim3(DMODEL / 32, DMODEL / 32), tb>>>(wq, wqh, wql, DMODEL, DMODEL);
    transpose_split_kernel<<<dim3(KV_DIM / 32, DMODEL / 32), tb>>>(wk, kvth, kvtl, DMODEL, KV_DIM);
    transpose_split_kernel<<<dim3(KV_DIM / 32, DMODEL / 32), tb>>>(
        wv, kvth + (size_t)KV_DIM * DMODEL, kvtl + (size_t)KV_DIM * DMODEL, DMODEL, KV_DIM);
    transpose_split_kernel<<<dim3(DMODEL / 32, DMODEL / 32), tb>>>(wo, woh, wol, DMODEL, DMODEL);

    // 3) Projections
    mma_gemm_kernel<256><<<dim3(DMODEL / 256, S_LEN / 128), 256, GEMM_SMEM_256>>>(
        hh, hl, wqh, wql, nullptr, pq, DMODEL, DMODEL);
    mma_gemm_kernel<128><<<dim3(2 * KV_DIM / 128, S_LEN / 128), 256, GEMM_SMEM_128>>>(
        hh, hl, kvth, kvtl, nullptr, pkv, 2 * KV_DIM, DMODEL);

    // 4) RoPE + splits
    {
        const int tq = S_LEN * HQ * 16;
        rope_split_kernel<<<(tq + 255) / 256, 256>>>(pq, DMODEL, qh, ql, DMODEL, HQ, 0.125f, tq);
        const int tk = S_LEN * HKV * 16;
        rope_split_kernel<<<(tk + 255) / 256, 256>>>(pkv, 2 * KV_DIM, kh, kl, KV_DIM, HKV, 1.0f, tk);
        split_v_kernel<<<(S_LEN * KV_DIM / 2 + 255) / 256, 256>>>(pkv, vh, vl);
    }

    // 5) Attention (grid swapped for causal wave balance)
    attn_mma_kernel<<<dim3(S_LEN / 128, HQ), 256>>>(qh, ql, kh, kl, vh, vl, oh, ol);

    // 6) Output projection + residual
    mma_gemm_kernel<256><<<dim3(DMODEL / 256, S_LEN / 128), 256, GEMM_SMEM_256>>>(
        oh, ol, woh, wol, x, out, DMODEL, DMODEL);
}